// round 1
// baseline (speedup 1.0000x reference)
#include <cuda_runtime.h>

#define N_NODES 100000
#define F_IN    500
#define HID     256
#define C_OUT   40
#define ALPHA0  0.1f

// Scratch (allocation-free rule: __device__ globals)
__device__ float g_h1[(size_t)N_NODES * HID];   // 102.4 MB
__device__ float g_h2[(size_t)N_NODES * C_OUT]; // 16 MB

// ---------------------------------------------------------------------------
// GEMM1: h1 = relu(x[N,500] @ W1[500,256] + b1)
// 64x64 tile, BK=16, 256 threads, 4x4 microtile, float4 shared reads.
// ---------------------------------------------------------------------------
#define BM 64
#define BN 64
#define BK 16

__global__ __launch_bounds__(256) void gemm1_relu_kernel(
    const float* __restrict__ x,
    const float* __restrict__ W1,
    const float* __restrict__ b1)
{
    __shared__ float As[BK][BM];   // A stored transposed: As[k][row]
    __shared__ float Bs[BK][BN];

    const int tid = threadIdx.x;
    const int blockRow = blockIdx.x * BM;
    const int blockCol = blockIdx.y * BN;

    const int ty = tid / 16;       // 0..15
    const int tx = tid % 16;       // 0..15

    // A-load mapping: 64 rows x 16 k, 4 consecutive k per thread
    const int lr = tid / 4;            // 0..63
    const int lk = (tid % 4) * 4;      // 0,4,8,12
    // B-load mapping: 16 k-rows x 64 cols, 4 consecutive cols per thread
    const int wr = tid / 16;           // 0..15
    const int wc = (tid % 16) * 4;     // 0..60

    float acc[4][4] = {};

    for (int k0 = 0; k0 < F_IN; k0 += BK) {
        // Load A tile (guard row and k; F_IN=500 not a multiple of 16)
        {
            const int grow = blockRow + lr;
            #pragma unroll
            for (int j = 0; j < 4; j++) {
                const int gk = k0 + lk + j;
                float v = 0.f;
                if (grow < N_NODES && gk < F_IN)
                    v = x[(size_t)grow * F_IN + gk];
                As[lk + j][lr] = v;
            }
        }
        // Load B tile (cols always in-bounds: HID=256 divisible by 64)
        {
            const int gk = k0 + wr;
            float4 v = make_float4(0.f, 0.f, 0.f, 0.f);
            if (gk < F_IN)
                v = *reinterpret_cast<const float4*>(
                        W1 + (size_t)gk * HID + blockCol + wc);
            *reinterpret_cast<float4*>(&Bs[wr][wc]) = v;
        }
        __syncthreads();

        #pragma unroll
        for (int k = 0; k < BK; k++) {
            const float4 a4 = *reinterpret_cast<const float4*>(&As[k][ty * 4]);
            const float4 b4 = *reinterpret_cast<const float4*>(&Bs[k][tx * 4]);
            const float a[4] = {a4.x, a4.y, a4.z, a4.w};
            const float b[4] = {b4.x, b4.y, b4.z, b4.w};
            #pragma unroll
            for (int i = 0; i < 4; i++)
                #pragma unroll
                for (int j = 0; j < 4; j++)
                    acc[i][j] = fmaf(a[i], b[j], acc[i][j]);
        }
        __syncthreads();
    }

    // Epilogue: + bias, ReLU, store
    #pragma unroll
    for (int i = 0; i < 4; i++) {
        const int grow = blockRow + ty * 4 + i;
        if (grow >= N_NODES) continue;
        #pragma unroll
        for (int j = 0; j < 4; j++) {
            const int gcol = blockCol + tx * 4 + j;
            const float v = acc[i][j] + b1[gcol];
            g_h1[(size_t)grow * HID + gcol] = fmaxf(v, 0.f);
        }
    }
}

// ---------------------------------------------------------------------------
// GEMM2: h2 = h1[N,256] @ W2[256,40] + b2 ; also d_out = ALPHA0 * h2
// 320 threads (8 row-groups x 40 cols), 32 rows/block, BK=32.
// ---------------------------------------------------------------------------
__global__ __launch_bounds__(320) void gemm2_kernel(
    const float* __restrict__ W2,
    const float* __restrict__ b2,
    float* __restrict__ out)
{
    __shared__ float Hs[32][33];      // [row][k], padded
    __shared__ float Ws[32][C_OUT];   // [k][col]

    const int tid  = threadIdx.x;
    const int row0 = blockIdx.x * 32;
    const int col  = tid % C_OUT;     // 0..39
    const int rg   = tid / C_OUT;     // 0..7

    float acc[4] = {0.f, 0.f, 0.f, 0.f};

    for (int k0 = 0; k0 < HID; k0 += 32) {
        for (int i = tid; i < 32 * 32; i += 320) {
            const int r = i / 32, k = i % 32;
            const int grow = row0 + r;
            Hs[r][k] = (grow < N_NODES) ? g_h1[(size_t)grow * HID + k0 + k] : 0.f;
        }
        for (int i = tid; i < 32 * C_OUT; i += 320) {
            const int k = i / C_OUT, c = i % C_OUT;
            Ws[k][c] = W2[(size_t)(k0 + k) * C_OUT + c];
        }
        __syncthreads();

        #pragma unroll
        for (int k = 0; k < 32; k++) {
            const float w = Ws[k][col];
            #pragma unroll
            for (int i = 0; i < 4; i++)
                acc[i] = fmaf(Hs[rg + i * 8][k], w, acc[i]);
        }
        __syncthreads();
    }

    const float bias = b2[col];
    #pragma unroll
    for (int i = 0; i < 4; i++) {
        const int grow = row0 + rg + i * 8;
        if (grow < N_NODES) {
            const float v = acc[i] + bias;
            g_h2[(size_t)grow * C_OUT + col] = v;
            out[(size_t)grow * C_OUT + col] = ALPHA0 * v;
        }
    }
}

// ---------------------------------------------------------------------------
// Edge scatter-add: out[row] += val * h2[col]  (10 threads/edge, float4 each)
// ---------------------------------------------------------------------------
__global__ __launch_bounds__(256) void edge_kernel(
    const int* __restrict__ erow,
    const int* __restrict__ ecol,
    const float* __restrict__ eval,
    float* __restrict__ out,
    long long num_edges)
{
    const long long gid = (long long)blockIdx.x * blockDim.x + threadIdx.x;
    const long long e = gid / 10;
    if (e >= num_edges) return;
    const int sub = (int)(gid % 10);

    const int r = erow[e];
    const int c = ecol[e];
    const float v = eval[e];

    const float4 h = reinterpret_cast<const float4*>(g_h2 + (size_t)c * C_OUT)[sub];
    float* o = out + (size_t)r * C_OUT + sub * 4;
    atomicAdd(o + 0, v * h.x);
    atomicAdd(o + 1, v * h.y);
    atomicAdd(o + 2, v * h.z);
    atomicAdd(o + 3, v * h.w);
}

// ---------------------------------------------------------------------------
// log_softmax over C=40, one warp per row, in place.
// ---------------------------------------------------------------------------
__global__ __launch_bounds__(256) void logsoftmax_kernel(float* __restrict__ out)
{
    const int warp = (blockIdx.x * blockDim.x + threadIdx.x) >> 5;
    const int lane = threadIdx.x & 31;
    if (warp >= N_NODES) return;

    float* row = out + (size_t)warp * C_OUT;
    const float v0 = (lane < C_OUT) ? row[lane] : -__int_as_float(0x7f800000);
    const float v1 = (lane + 32 < C_OUT) ? row[lane + 32] : -__int_as_float(0x7f800000);

    float m = fmaxf(v0, v1);
    #pragma unroll
    for (int o = 16; o > 0; o >>= 1)
        m = fmaxf(m, __shfl_xor_sync(0xffffffffu, m, o));

    float s = ((lane < C_OUT) ? expf(v0 - m) : 0.f)
            + ((lane + 32 < C_OUT) ? expf(v1 - m) : 0.f);
    #pragma unroll
    for (int o = 16; o > 0; o >>= 1)
        s += __shfl_xor_sync(0xffffffffu, s, o);

    const float lse = m + logf(s);
    if (lane < C_OUT) row[lane] = v0 - lse;
    if (lane + 32 < C_OUT) row[lane + 32] = v1 - lse;
}

// ---------------------------------------------------------------------------
// Inputs (metadata order): x, W1, b1, W2, b2, edge_row, edge_col, edge_val
// ---------------------------------------------------------------------------
extern "C" void kernel_launch(void* const* d_in, const int* in_sizes, int n_in,
                              void* d_out, int out_size)
{
    const float* x    = (const float*)d_in[0];
    const float* W1   = (const float*)d_in[1];
    const float* b1   = (const float*)d_in[2];
    const float* W2   = (const float*)d_in[3];
    const float* b2   = (const float*)d_in[4];
    const int*   erow = (const int*)d_in[5];
    const int*   ecol = (const int*)d_in[6];
    const float* eval = (const float*)d_in[7];
    float* out = (float*)d_out;

    const long long E = in_sizes[5];

    // GEMM1 + ReLU
    {
        dim3 grid((N_NODES + BM - 1) / BM, HID / BN);
        gemm1_relu_kernel<<<grid, 256>>>(x, W1, b1);
    }
    // GEMM2 (+ init out = alpha * h2)
    {
        dim3 grid((N_NODES + 31) / 32);
        gemm2_kernel<<<grid, 320>>>(W2, b2, out);
    }
    // Edge scatter-add
    {
        const long long total = E * 10;
        const int blocks = (int)((total + 255) / 256);
        edge_kernel<<<blocks, 256>>>(erow, ecol, eval, out, E);
    }
    // log_softmax
    {
        const long long threads = (long long)N_NODES * 32;
        const int blocks = (int)((threads + 255) / 256);
        logsoftmax_kernel<<<blocks, 256>>>(out);
    }
}

// round 2
// speedup vs baseline: 1.2938x; 1.2938x over previous
#include <cuda_runtime.h>

#define N_NODES 100000
#define F_IN    500
#define HID     256
#define C_OUT   40
#define ALPHA0  0.1f

// Scratch (allocation-free rule: __device__ globals)
__device__ float g_h1[(size_t)N_NODES * HID];   // 102.4 MB
__device__ float g_h2[(size_t)N_NODES * C_OUT]; // 16 MB

// ---------------------------------------------------------------------------
// f32x2 packed-FMA helpers (sm_103a: FFMA2 only reachable via PTX)
// ---------------------------------------------------------------------------
#define PACK_F32X2(d, lo, hi) \
    asm("mov.b64 %0, {%1, %2};" : "=l"(d) : "r"(__float_as_uint(lo)), "r"(__float_as_uint(hi)))

#define UNPACK_F32X2(lo, hi, v) \
    asm("mov.b64 {%0, %1}, %2;" : "=r"(lo), "=r"(hi) : "l"(v))

#define FMA_F32X2(d, a, b, c) \
    asm("fma.rn.f32x2 %0, %1, %2, %3;" : "=l"(d) : "l"(a), "l"(b), "l"(c))

// ---------------------------------------------------------------------------
// GEMM1: h1 = relu(x[N,500] @ W1[500,256] + b1)
// BM=128, BN=128, BK=8, 256 threads, 8x8 microtile, f32x2 FMAs.
// A pairs = consecutive rows (natural in As[k][row]).
// B pairs = duplicated (b,b) in smem; thread cols interleaved (tc + 16m)
// so per-pair LDS.64 lanes are conflict-free.
// Single-sync register-prefetch double buffering.
// ---------------------------------------------------------------------------
#define BM 128
#define BN 128
#define BK 8
#define NT ((F_IN + BK - 1) / BK)   // 63

__global__ __launch_bounds__(256, 2) void gemm1_relu_kernel(
    const float* __restrict__ x,
    const float* __restrict__ W1,
    const float* __restrict__ b1)
{
    __shared__ float As[2][BK][BM];        // 2 * 4KB
    __shared__ float Bsd[2][BK][2 * BN];   // 2 * 8KB (duplicated pairs)

    const int tid = threadIdx.x;
    const int blockRow = blockIdx.x * BM;
    const int blockCol = blockIdx.y * BN;

    // compute mapping: 16 row-groups x 16 col-lanes
    const int tr = tid >> 4;   // 0..15 -> rows tr*8 .. tr*8+7
    const int tc = tid & 15;   // 0..15 -> cols tc + 16m, m=0..7

    // A global-load mapping: 128 rows x 8 k, float4 of k per thread
    const int ar  = tid >> 1;          // 0..127
    const int akk = (tid & 1) * 4;     // 0 or 4
    const int arow = blockRow + ar;
    const bool arow_ok = (arow < N_NODES);
    // B global-load mapping: 8 k-rows x 128 cols, float4 of cols per thread
    const int bk  = tid >> 5;          // 0..7
    const int bc4 = (tid & 31) * 4;    // 0..124

    unsigned long long acc[4][8];
    unsigned long long zero_u64;
    PACK_F32X2(zero_u64, 0.f, 0.f);
    #pragma unroll
    for (int i = 0; i < 4; i++)
        #pragma unroll
        for (int m = 0; m < 8; m++)
            acc[i][m] = zero_u64;

    // ---- prologue: load tile 0 ----
    float4 pa = make_float4(0.f, 0.f, 0.f, 0.f);
    float4 pb = make_float4(0.f, 0.f, 0.f, 0.f);
    if (arow_ok && akk < F_IN)
        pa = *reinterpret_cast<const float4*>(x + (size_t)arow * F_IN + akk);
    // bk < 8 <= F_IN always on tile 0
    pb = *reinterpret_cast<const float4*>(W1 + (size_t)bk * HID + blockCol + bc4);

    {
        As[0][akk + 0][ar] = pa.x;
        As[0][akk + 1][ar] = pa.y;
        As[0][akk + 2][ar] = pa.z;
        As[0][akk + 3][ar] = pa.w;
        float* bd = &Bsd[0][bk][2 * bc4];
        *reinterpret_cast<float4*>(bd)     = make_float4(pb.x, pb.x, pb.y, pb.y);
        *reinterpret_cast<float4*>(bd + 4) = make_float4(pb.z, pb.z, pb.w, pb.w);
    }
    __syncthreads();

    for (int t = 0; t < NT; t++) {
        const int cur = t & 1;
        const int nxt = cur ^ 1;

        // prefetch next tile into registers
        if (t + 1 < NT) {
            const int k0 = (t + 1) * BK;
            pa = make_float4(0.f, 0.f, 0.f, 0.f);
            pb = make_float4(0.f, 0.f, 0.f, 0.f);
            if (arow_ok && (k0 + akk) < F_IN)   // k0+akk multiple of 4, so +3 stays < F_IN
                pa = *reinterpret_cast<const float4*>(x + (size_t)arow * F_IN + k0 + akk);
            if ((k0 + bk) < F_IN)
                pb = *reinterpret_cast<const float4*>(W1 + (size_t)(k0 + bk) * HID + blockCol + bc4);
        }

        // compute on current buffer
        #pragma unroll
        for (int k = 0; k < BK; k++) {
            const float4 a03 = *reinterpret_cast<const float4*>(&As[cur][k][tr * 8]);
            const float4 a47 = *reinterpret_cast<const float4*>(&As[cur][k][tr * 8 + 4]);
            unsigned long long A[4];
            PACK_F32X2(A[0], a03.x, a03.y);
            PACK_F32X2(A[1], a03.z, a03.w);
            PACK_F32X2(A[2], a47.x, a47.y);
            PACK_F32X2(A[3], a47.z, a47.w);
            unsigned long long B[8];
            #pragma unroll
            for (int m = 0; m < 8; m++) {
                const float2 bv = *reinterpret_cast<const float2*>(&Bsd[cur][k][2 * (tc + 16 * m)]);
                PACK_F32X2(B[m], bv.x, bv.y);
            }
            #pragma unroll
            for (int i = 0; i < 4; i++)
                #pragma unroll
                for (int m = 0; m < 8; m++)
                    FMA_F32X2(acc[i][m], A[i], B[m], acc[i][m]);
        }

        // store prefetched tile into next buffer
        if (t + 1 < NT) {
            As[nxt][akk + 0][ar] = pa.x;
            As[nxt][akk + 1][ar] = pa.y;
            As[nxt][akk + 2][ar] = pa.z;
            As[nxt][akk + 3][ar] = pa.w;
            float* bd = &Bsd[nxt][bk][2 * bc4];
            *reinterpret_cast<float4*>(bd)     = make_float4(pb.x, pb.x, pb.y, pb.y);
            *reinterpret_cast<float4*>(bd + 4) = make_float4(pb.z, pb.z, pb.w, pb.w);
        }
        __syncthreads();
    }

    // ---- epilogue: bias + ReLU + store ----
    #pragma unroll
    for (int m = 0; m < 8; m++) {
        const int col = blockCol + tc + 16 * m;
        const float bias = b1[col];
        #pragma unroll
        for (int i = 0; i < 4; i++) {
            const int r0 = blockRow + tr * 8 + 2 * i;
            unsigned int ulo, uhi;
            UNPACK_F32X2(ulo, uhi, acc[i][m]);
            if (r0 < N_NODES)
                g_h1[(size_t)r0 * HID + col] = fmaxf(__uint_as_float(ulo) + bias, 0.f);
            if (r0 + 1 < N_NODES)
                g_h1[(size_t)(r0 + 1) * HID + col] = fmaxf(__uint_as_float(uhi) + bias, 0.f);
        }
    }
}

// ---------------------------------------------------------------------------
// GEMM2: h2 = h1[N,256] @ W2[256,40] + b2 ; also d_out = ALPHA0 * h2
// ---------------------------------------------------------------------------
__global__ __launch_bounds__(320) void gemm2_kernel(
    const float* __restrict__ W2,
    const float* __restrict__ b2,
    float* __restrict__ out)
{
    __shared__ float Hs[32][33];
    __shared__ float Ws[32][C_OUT];

    const int tid  = threadIdx.x;
    const int row0 = blockIdx.x * 32;
    const int col  = tid % C_OUT;
    const int rg   = tid / C_OUT;

    float acc[4] = {0.f, 0.f, 0.f, 0.f};

    for (int k0 = 0; k0 < HID; k0 += 32) {
        for (int i = tid; i < 32 * 32; i += 320) {
            const int r = i / 32, k = i % 32;
            const int grow = row0 + r;
            Hs[r][k] = (grow < N_NODES) ? g_h1[(size_t)grow * HID + k0 + k] : 0.f;
        }
        for (int i = tid; i < 32 * C_OUT; i += 320) {
            const int k = i / C_OUT, c = i % C_OUT;
            Ws[k][c] = W2[(size_t)(k0 + k) * C_OUT + c];
        }
        __syncthreads();

        #pragma unroll
        for (int k = 0; k < 32; k++) {
            const float w = Ws[k][col];
            #pragma unroll
            for (int i = 0; i < 4; i++)
                acc[i] = fmaf(Hs[rg + i * 8][k], w, acc[i]);
        }
        __syncthreads();
    }

    const float bias = b2[col];
    #pragma unroll
    for (int i = 0; i < 4; i++) {
        const int grow = row0 + rg + i * 8;
        if (grow < N_NODES) {
            const float v = acc[i] + bias;
            g_h2[(size_t)grow * C_OUT + col] = v;
            out[(size_t)grow * C_OUT + col] = ALPHA0 * v;
        }
    }
}

// ---------------------------------------------------------------------------
// Edge scatter-add: out[row] += val * h2[col]
// 10 threads/edge; each thread: 1 float4 gather + 1 red.global.add.v4.f32
// ---------------------------------------------------------------------------
__global__ __launch_bounds__(256) void edge_kernel(
    const int* __restrict__ erow,
    const int* __restrict__ ecol,
    const float* __restrict__ eval,
    float* __restrict__ out,
    long long num_edges)
{
    const long long gid = (long long)blockIdx.x * blockDim.x + threadIdx.x;
    const long long e = gid / 10;
    if (e >= num_edges) return;
    const int sub = (int)(gid % 10);

    const int r = erow[e];
    const int c = ecol[e];
    const float v = eval[e];

    const float4 h = reinterpret_cast<const float4*>(g_h2 + (size_t)c * C_OUT)[sub];
    float* o = out + (size_t)r * C_OUT + sub * 4;
    asm volatile("red.global.add.v4.f32 [%0], {%1, %2, %3, %4};"
                 :: "l"(o), "f"(v * h.x), "f"(v * h.y), "f"(v * h.z), "f"(v * h.w)
                 : "memory");
}

// ---------------------------------------------------------------------------
// log_softmax over C=40, one warp per row, in place.
// ---------------------------------------------------------------------------
__global__ __launch_bounds__(256) void logsoftmax_kernel(float* __restrict__ out)
{
    const int warp = (blockIdx.x * blockDim.x + threadIdx.x) >> 5;
    const int lane = threadIdx.x & 31;
    if (warp >= N_NODES) return;

    float* row = out + (size_t)warp * C_OUT;
    const float v0 = (lane < C_OUT) ? row[lane] : -__int_as_float(0x7f800000);
    const float v1 = (lane + 32 < C_OUT) ? row[lane + 32] : -__int_as_float(0x7f800000);

    float m = fmaxf(v0, v1);
    #pragma unroll
    for (int o = 16; o > 0; o >>= 1)
        m = fmaxf(m, __shfl_xor_sync(0xffffffffu, m, o));

    float s = ((lane < C_OUT) ? expf(v0 - m) : 0.f)
            + ((lane + 32 < C_OUT) ? expf(v1 - m) : 0.f);
    #pragma unroll
    for (int o = 16; o > 0; o >>= 1)
        s += __shfl_xor_sync(0xffffffffu, s, o);

    const float lse = m + logf(s);
    if (lane < C_OUT) row[lane] = v0 - lse;
    if (lane + 32 < C_OUT) row[lane + 32] = v1 - lse;
}

// ---------------------------------------------------------------------------
// Inputs (metadata order): x, W1, b1, W2, b2, edge_row, edge_col, edge_val
// ---------------------------------------------------------------------------
extern "C" void kernel_launch(void* const* d_in, const int* in_sizes, int n_in,
                              void* d_out, int out_size)
{
    const float* x    = (const float*)d_in[0];
    const float* W1   = (const float*)d_in[1];
    const float* b1   = (const float*)d_in[2];
    const float* W2   = (const float*)d_in[3];
    const float* b2   = (const float*)d_in[4];
    const int*   erow = (const int*)d_in[5];
    const int*   ecol = (const int*)d_in[6];
    const float* eval = (const float*)d_in[7];
    float* out = (float*)d_out;

    const long long E = in_sizes[5];

    // GEMM1 + ReLU (f32x2)
    {
        dim3 grid((N_NODES + BM - 1) / BM, HID / BN);
        gemm1_relu_kernel<<<grid, 256>>>(x, W1, b1);
    }
    // GEMM2 (+ init out = alpha * h2)
    {
        dim3 grid((N_NODES + 31) / 32);
        gemm2_kernel<<<grid, 320>>>(W2, b2, out);
    }
    // Edge scatter-add (vector red)
    {
        const long long total = E * 10;
        const int blocks = (int)((total + 255) / 256);
        edge_kernel<<<blocks, 256>>>(erow, ecol, eval, out, E);
    }
    // log_softmax
    {
        const long long threads = (long long)N_NODES * 32;
        const int blocks = (int)((threads + 255) / 256);
        logsoftmax_kernel<<<blocks, 256>>>(out);
    }
}

// round 4
// speedup vs baseline: 2.5862x; 1.9989x over previous
#include <cuda_runtime.h>
#include <cuda_bf16.h>
#include <cstdint>

#define N_NODES 100000
#define F_IN    500
#define HID     256
#define C_OUT   40
#define ALPHA0  0.1f
#define K_PAD   512
#define BK      32
#define NCHUNK  16
#define BM      128
#define N2      64

// ---------------------------------------------------------------------------
// Device-global scratch (allocation-free rule)
// ---------------------------------------------------------------------------
__device__ float g_h2[(size_t)N_NODES * C_OUT];                       // 16 MB
__device__ __align__(16) __nv_bfloat16 g_w1t_hi[HID * K_PAD];         // W1^T hi (bias at k=500)
__device__ __align__(16) __nv_bfloat16 g_w1t_lo[HID * K_PAD];
__device__ __align__(16) __nv_bfloat16 g_w2t_hi[N2 * HID];            // W2^T (n padded 40->64)
__device__ __align__(16) __nv_bfloat16 g_w2t_lo[N2 * HID];

// ---------------------------------------------------------------------------
// Helpers
// ---------------------------------------------------------------------------
__device__ __forceinline__ uint32_t smem_u32(const void* p) {
    uint32_t a;
    asm("{ .reg .u64 t; cvta.to.shared.u64 t, %1; cvt.u32.u64 %0, t; }" : "=r"(a) : "l"(p));
    return a;
}

// pack (lo, hi) floats into bf16x2 word: lower halfword = lo
__device__ __forceinline__ uint32_t pack_bf2(float lo, float hi) {
    uint32_t r;
    asm("cvt.rn.bf16x2.f32 %0, %1, %2;" : "=r"(r) : "f"(hi), "f"(lo));
    return r;
}
__device__ __forceinline__ float bf_lo(uint32_t w) { return __uint_as_float(w << 16); }
__device__ __forceinline__ float bf_hi(uint32_t w) { return __uint_as_float(w & 0xffff0000u); }

__device__ __forceinline__ void mma_bf16(float d[4], const uint32_t a[4], const uint32_t b[2]) {
    asm volatile("mma.sync.aligned.m16n8k16.row.col.f32.bf16.bf16.f32 "
                 "{%0,%1,%2,%3},{%4,%5,%6,%7},{%8,%9},{%0,%1,%2,%3};"
                 : "+f"(d[0]), "+f"(d[1]), "+f"(d[2]), "+f"(d[3])
                 : "r"(a[0]), "r"(a[1]), "r"(a[2]), "r"(a[3]), "r"(b[0]), "r"(b[1]));
}

#define CP_ASYNC16(dst, src) \
    asm volatile("cp.async.cg.shared.global [%0], [%1], 16;" :: "r"(dst), "l"(src))
#define CP_COMMIT() asm volatile("cp.async.commit_group;" ::: "memory")
#define CP_WAIT0()  asm volatile("cp.async.wait_group 0;" ::: "memory")

// ---------------------------------------------------------------------------
// Dynamic SMEM layout (bytes)
// Stage 1 (GEMM1 mainloop), two buffers of 61440B:
//   sA_hi[128][40]b16 (10240) | sA_lo (10240) | sB_hi[256][40] (20480) | sB_lo (20480)
// Stage 2 (GEMM2), reusing the whole region:
//   sH_hi[128][264] (67584) | sH_lo (67584) | sW_hi[64][264] (33792) | sW_lo (33792)
// ---------------------------------------------------------------------------
#define APAD 40
#define SA_HI(b) ((b) * 61440)
#define SA_LO(b) ((b) * 61440 + 10240)
#define SB_HI(b) ((b) * 61440 + 20480)
#define SB_LO(b) ((b) * 61440 + 40960)
#define HPAD 264
#define SH_HI 0
#define SH_LO 67584
#define SW_HI 135168
#define SW_LO 168960
#define DSMEM_BYTES 202752

// ---------------------------------------------------------------------------
// Prep: bf16 hi/lo images of W1^T (bias folded at k=500) and W2^T (pad 40->64)
// ---------------------------------------------------------------------------
__global__ void prep_kernel(const float* __restrict__ W1,
                            const float* __restrict__ b1,
                            const float* __restrict__ W2)
{
    const int idx = blockIdx.x * blockDim.x + threadIdx.x;
    if (idx < HID * K_PAD) {
        const int n = idx >> 9;
        const int k = idx & (K_PAD - 1);
        float v = 0.f;
        if (k < F_IN)       v = W1[(size_t)k * HID + n];
        else if (k == F_IN) v = b1[n];
        const __nv_bfloat16 h = __float2bfloat16_rn(v);
        g_w1t_hi[idx] = h;
        g_w1t_lo[idx] = __float2bfloat16_rn(v - __bfloat162float(h));
    } else {
        const int i = idx - HID * K_PAD;
        if (i < N2 * HID) {
            const int n = i >> 8;
            const int k = i & 255;
            const float v = (n < C_OUT) ? W2[(size_t)k * C_OUT + n] : 0.f;
            const __nv_bfloat16 h = __float2bfloat16_rn(v);
            g_w2t_hi[i] = h;
            g_w2t_lo[i] = __float2bfloat16_rn(v - __bfloat162float(h));
        }
    }
}

// ---------------------------------------------------------------------------
// Fused GEMM1(+bias+ReLU)+GEMM2(+bias) via mma.sync bf16 split (3 terms).
// ---------------------------------------------------------------------------
#define LOADA(c) do {                                                          \
    const int gk = (c) * BK + akq;                                             \
    _Pragma("unroll")                                                          \
    for (int rr = 0; rr < 4; rr++) {                                           \
        const int grow = blockRow + ar + rr * 32;                              \
        float4 v = make_float4(0.f, 0.f, 0.f, 0.f);                            \
        if (grow < N_NODES) {                                                  \
            if (gk + 3 < F_IN) {                                               \
                v = *(const float4*)(x + (size_t)grow * F_IN + gk);            \
            } else {                                                           \
                const float* xr = x + (size_t)grow * F_IN;                     \
                v.x = (gk + 0 < F_IN) ? xr[gk + 0] : (gk + 0 == F_IN ? 1.f : 0.f); \
                v.y = (gk + 1 < F_IN) ? xr[gk + 1] : (gk + 1 == F_IN ? 1.f : 0.f); \
                v.z = (gk + 2 < F_IN) ? xr[gk + 2] : (gk + 2 == F_IN ? 1.f : 0.f); \
                v.w = (gk + 3 < F_IN) ? xr[gk + 3] : (gk + 3 == F_IN ? 1.f : 0.f); \
            }                                                                  \
        }                                                                      \
        av[rr] = v;                                                            \
    }                                                                          \
} while (0)

#define STSA(buf) do {                                                         \
    _Pragma("unroll")                                                          \
    for (int rr = 0; rr < 4; rr++) {                                           \
        const int o = (ar + rr * 32) * APAD + akq;                             \
        const uint32_t h0 = pack_bf2(av[rr].x, av[rr].y);                      \
        const uint32_t h1 = pack_bf2(av[rr].z, av[rr].w);                      \
        const uint32_t l0 = pack_bf2(av[rr].x - bf_lo(h0), av[rr].y - bf_hi(h0)); \
        const uint32_t l1 = pack_bf2(av[rr].z - bf_lo(h1), av[rr].w - bf_hi(h1)); \
        *(uint2*)(dsm + SA_HI(buf) + o * 2) = make_uint2(h0, h1);              \
        *(uint2*)(dsm + SA_LO(buf) + o * 2) = make_uint2(l0, l1);              \
    }                                                                          \
} while (0)

#define CPB(c, buf) do {                                                       \
    const uint32_t dhi = smbase + SB_HI(buf) + tid * (APAD * 2);               \
    const uint32_t dlo = smbase + SB_LO(buf) + tid * (APAD * 2);               \
    const __nv_bfloat16* shi = g_w1t_hi + (size_t)tid * K_PAD + (c) * BK;      \
    const __nv_bfloat16* slo = g_w1t_lo + (size_t)tid * K_PAD + (c) * BK;      \
    _Pragma("unroll")                                                          \
    for (int q = 0; q < 4; q++) {                                              \
        CP_ASYNC16(dhi + q * 16, shi + q * 8);                                 \
        CP_ASYNC16(dlo + q * 16, slo + q * 8);                                 \
    }                                                                          \
} while (0)

#define MMACHUNK(buf) do {                                                     \
    _Pragma("unroll")                                                          \
    for (int s = 0; s < 2; s++) {                                              \
        const int kk = s * 16 + tid4 * 2;                                      \
        uint32_t Bh[8][2], Bl[8][2];                                           \
        _Pragma("unroll")                                                      \
        for (int j = 0; j < 8; j++) {                                          \
            const int o = (wn * 64 + j * 8 + grp) * APAD + kk;                 \
            Bh[j][0] = *(const uint32_t*)(dsm + SB_HI(buf) + o * 2);           \
            Bh[j][1] = *(const uint32_t*)(dsm + SB_HI(buf) + (o + 8) * 2);     \
            Bl[j][0] = *(const uint32_t*)(dsm + SB_LO(buf) + o * 2);           \
            Bl[j][1] = *(const uint32_t*)(dsm + SB_LO(buf) + (o + 8) * 2);     \
        }                                                                      \
        _Pragma("unroll")                                                      \
        for (int i = 0; i < 4; i++) {                                          \
            const int o1 = (wm * 64 + i * 16 + grp) * APAD + kk;               \
            const int o2 = o1 + 8 * APAD;                                      \
            uint32_t Ah[4], Al[4];                                             \
            Ah[0] = *(const uint32_t*)(dsm + SA_HI(buf) + o1 * 2);             \
            Ah[1] = *(const uint32_t*)(dsm + SA_HI(buf) + o2 * 2);             \
            Ah[2] = *(const uint32_t*)(dsm + SA_HI(buf) + (o1 + 8) * 2);       \
            Ah[3] = *(const uint32_t*)(dsm + SA_HI(buf) + (o2 + 8) * 2);       \
            Al[0] = *(const uint32_t*)(dsm + SA_LO(buf) + o1 * 2);             \
            Al[1] = *(const uint32_t*)(dsm + SA_LO(buf) + o2 * 2);             \
            Al[2] = *(const uint32_t*)(dsm + SA_LO(buf) + (o1 + 8) * 2);       \
            Al[3] = *(const uint32_t*)(dsm + SA_LO(buf) + (o2 + 8) * 2);       \
            _Pragma("unroll")                                                  \
            for (int j = 0; j < 8; j++) {                                      \
                mma_bf16(acc[i][j], Ah, Bh[j]);                                \
                mma_bf16(acc[i][j], Ah, Bl[j]);                                \
                mma_bf16(acc[i][j], Al, Bh[j]);                                \
            }                                                                  \
        }                                                                      \
    }                                                                          \
} while (0)

__global__ void __launch_bounds__(256, 1) fused_kernel(
    const float* __restrict__ x,
    const float* __restrict__ b2,
    float* __restrict__ out)
{
    extern __shared__ char dsm[];
    __shared__ float s_b2[C_OUT];
    const uint32_t smbase = smem_u32(dsm);
    const int tid  = threadIdx.x;
    const int lane = tid & 31, wid = tid >> 5;
    const int grp  = lane >> 2, tid4 = lane & 3;
    const int wm   = wid >> 2, wn = wid & 3;
    const int blockRow = blockIdx.x * BM;

    if (tid < C_OUT) s_b2[tid] = b2[tid];

    // A global-load mapping: 32 rows x 8 threads, 4 floats each; 4 row passes
    const int ar  = tid >> 3;
    const int akq = (tid & 7) * 4;

    float acc[4][8][4];
    #pragma unroll
    for (int i = 0; i < 4; i++)
        #pragma unroll
        for (int j = 0; j < 8; j++)
            #pragma unroll
            for (int q = 0; q < 4; q++)
                acc[i][j][q] = 0.f;

    float4 av[4];

    // ---- prologue ----
    LOADA(0);
    CPB(0, 0);
    CP_COMMIT();
    STSA(0);
    CP_WAIT0();
    __syncthreads();

    // ---- GEMM1 mainloop over 16 K-chunks of 32 ----
    for (int c = 0; c < NCHUNK; c++) {
        const int cur = c & 1, nxt = cur ^ 1;
        if (c + 1 < NCHUNK) {
            LOADA(c + 1);
            CPB(c + 1, nxt);
            CP_COMMIT();
        }
        MMACHUNK(cur);
        if (c + 1 < NCHUNK) {
            STSA(nxt);
            CP_WAIT0();
        }
        __syncthreads();
    }

    // ---- epilogue 1: ReLU + split-bf16 -> sH ----
    #pragma unroll
    for (int i = 0; i < 4; i++) {
        const int r1 = wm * 64 + i * 16 + grp;
        #pragma unroll
        for (int j = 0; j < 8; j++) {
            const int col = wn * 64 + j * 8 + tid4 * 2;
            const float f0 = fmaxf(acc[i][j][0], 0.f), f1 = fmaxf(acc[i][j][1], 0.f);
            const float f2 = fmaxf(acc[i][j][2], 0.f), f3 = fmaxf(acc[i][j][3], 0.f);
            const uint32_t h0 = pack_bf2(f0, f1);
            const uint32_t l0 = pack_bf2(f0 - bf_lo(h0), f1 - bf_hi(h0));
            const uint32_t h1w = pack_bf2(f2, f3);
            const uint32_t l1w = pack_bf2(f2 - bf_lo(h1w), f3 - bf_hi(h1w));
            const int o1 = r1 * HPAD + col;
            const int o2 = o1 + 8 * HPAD;
            *(uint32_t*)(dsm + SH_HI + o1 * 2) = h0;
            *(uint32_t*)(dsm + SH_LO + o1 * 2) = l0;
            *(uint32_t*)(dsm + SH_HI + o2 * 2) = h1w;
            *(uint32_t*)(dsm + SH_LO + o2 * 2) = l1w;
        }
    }
    // ---- W2 images -> sW ----
    {
        const int n  = tid >> 2;
        const int kq = (tid & 3) * 64;
        #pragma unroll
        for (int q = 0; q < 8; q++) {
            const uint4 vh = *(const uint4*)(g_w2t_hi + n * HID + kq + q * 8);
            const uint4 vl = *(const uint4*)(g_w2t_lo + n * HID + kq + q * 8);
            *(uint4*)(dsm + SW_HI + (n * HPAD + kq + q * 8) * 2) = vh;
            *(uint4*)(dsm + SW_LO + (n * HPAD + kq + q * 8) * 2) = vl;
        }
    }
    __syncthreads();

    // ---- GEMM2: h2[128x64] = relu(h1)[128x256] @ W2t^T, 3-term split ----
    float acc2[8][4];
    #pragma unroll
    for (int j = 0; j < 8; j++)
        #pragma unroll
        for (int q = 0; q < 4; q++)
            acc2[j][q] = 0.f;

    #pragma unroll
    for (int s = 0; s < 16; s++) {
        const int kk = s * 16 + tid4 * 2;
        const int o1 = (wid * 16 + grp) * HPAD + kk;
        const int o2 = o1 + 8 * HPAD;
        uint32_t Ah[4], Al[4];
        Ah[0] = *(const uint32_t*)(dsm + SH_HI + o1 * 2);
        Ah[1] = *(const uint32_t*)(dsm + SH_HI + o2 * 2);
        Ah[2] = *(const uint32_t*)(dsm + SH_HI + (o1 + 8) * 2);
        Ah[3] = *(const uint32_t*)(dsm + SH_HI + (o2 + 8) * 2);
        Al[0] = *(const uint32_t*)(dsm + SH_LO + o1 * 2);
        Al[1] = *(const uint32_t*)(dsm + SH_LO + o2 * 2);
        Al[2] = *(const uint32_t*)(dsm + SH_LO + (o1 + 8) * 2);
        Al[3] = *(const uint32_t*)(dsm + SH_LO + (o2 + 8) * 2);
        #pragma unroll
        for (int j = 0; j < 8; j++) {
            const int ob = (j * 8 + grp) * HPAD + kk;
            uint32_t Bh[2], Bl[2];
            Bh[0] = *(const uint32_t*)(dsm + SW_HI + ob * 2);
            Bh[1] = *(const uint32_t*)(dsm + SW_HI + (ob + 8) * 2);
            Bl[0] = *(const uint32_t*)(dsm + SW_LO + ob * 2);
            Bl[1] = *(const uint32_t*)(dsm + SW_LO + (ob + 8) * 2);
            mma_bf16(acc2[j], Ah, Bh);
            mma_bf16(acc2[j], Ah, Bl);
            mma_bf16(acc2[j], Al, Bh);
        }
    }

    // ---- epilogue 2: h2 = D2 + b2 ; g_h2 = h2 ; out = alpha*h2 ----
    {
        const int r1 = blockRow + wid * 16 + grp;
        const int r2 = r1 + 8;
        #pragma unroll
        for (int j = 0; j < 5; j++) {          // cols 0..39 only
            const int col = j * 8 + tid4 * 2;
            const float b0 = s_b2[col], b1v = s_b2[col + 1];
            if (r1 < N_NODES) {
                const float v0 = acc2[j][0] + b0, v1 = acc2[j][1] + b1v;
                *(float2*)(g_h2 + (size_t)r1 * C_OUT + col) = make_float2(v0, v1);
                *(float2*)(out  + (size_t)r1 * C_OUT + col) = make_float2(ALPHA0 * v0, ALPHA0 * v1);
            }
            if (r2 < N_NODES) {
                const float v2 = acc2[j][2] + b0, v3 = acc2[j][3] + b1v;
                *(float2*)(g_h2 + (size_t)r2 * C_OUT + col) = make_float2(v2, v3);
                *(float2*)(out  + (size_t)r2 * C_OUT + col) = make_float2(ALPHA0 * v2, ALPHA0 * v3);
            }
        }
    }
}

// ---------------------------------------------------------------------------
// Edge scatter-add: out[row] += val * h2[col]  (10 threads/edge, red.v4)
// ---------------------------------------------------------------------------
__global__ void __launch_bounds__(256) edge_kernel(
    const int* __restrict__ erow,
    const int* __restrict__ ecol,
    const float* __restrict__ eval,
    float* __restrict__ out,
    long long num_edges)
{
    const long long gid = (long long)blockIdx.x * blockDim.x + threadIdx.x;
    const long long e = gid / 10;
    if (e >= num_edges) return;
    const int sub = (int)(gid % 10);

    const int r = erow[e];
    const int c = ecol[e];
    const float v = eval[e];

    const float4 h = reinterpret_cast<const float4*>(g_h2 + (size_t)c * C_OUT)[sub];
    float* o = out + (size_t)r * C_OUT + sub * 4;
    asm volatile("red.global.add.v4.f32 [%0], {%1, %2, %3, %4};"
                 :: "l"(o), "f"(v * h.x), "f"(v * h.y), "f"(v * h.z), "f"(v * h.w)
                 : "memory");
}

// ---------------------------------------------------------------------------
// log_softmax over C=40, one warp per row, in place.
// ---------------------------------------------------------------------------
__global__ void __launch_bounds__(256) logsoftmax_kernel(float* __restrict__ out)
{
    const int warp = (blockIdx.x * blockDim.x + threadIdx.x) >> 5;
    const int lane = threadIdx.x & 31;
    if (warp >= N_NODES) return;

    float* row = out + (size_t)warp * C_OUT;
    const float v0 = (lane < C_OUT) ? row[lane] : -__int_as_float(0x7f800000);
    const float v1 = (lane + 32 < C_OUT) ? row[lane + 32] : -__int_as_float(0x7f800000);

    float m = fmaxf(v0, v1);
    #pragma unroll
    for (int o = 16; o > 0; o >>= 1)
        m = fmaxf(m, __shfl_xor_sync(0xffffffffu, m, o));

    float s = ((lane < C_OUT) ? expf(v0 - m) : 0.f)
            + ((lane + 32 < C_OUT) ? expf(v1 - m) : 0.f);
    #pragma unroll
    for (int o = 16; o > 0; o >>= 1)
        s += __shfl_xor_sync(0xffffffffu, s, o);

    const float lse = m + logf(s);
    if (lane < C_OUT) row[lane] = v0 - lse;
    if (lane + 32 < C_OUT) row[lane + 32] = v1 - lse;
}

// ---------------------------------------------------------------------------
// Inputs: x, W1, b1, W2, b2, edge_row, edge_col, edge_val
// ---------------------------------------------------------------------------
extern "C" void kernel_launch(void* const* d_in, const int* in_sizes, int n_in,
                              void* d_out, int out_size)
{
    const float* x    = (const float*)d_in[0];
    const float* W1   = (const float*)d_in[1];
    const float* b1   = (const float*)d_in[2];
    const float* W2   = (const float*)d_in[3];
    const float* b2   = (const float*)d_in[4];
    const int*   erow = (const int*)d_in[5];
    const int*   ecol = (const int*)d_in[6];
    const float* eval = (const float*)d_in[7];
    float* out = (float*)d_out;

    const long long E = in_sizes[5];

    cudaFuncSetAttribute(fused_kernel,
                         cudaFuncAttributeMaxDynamicSharedMemorySize, DSMEM_BYTES);

    // prep weight images
    {
        const int total = HID * K_PAD + N2 * HID;
        prep_kernel<<<(total + 255) / 256, 256>>>(W1, b1, W2);
    }
    // fused GEMM1+GEMM2 (mma.sync bf16 split), writes g_h2 and out = alpha*h2
    {
        const int blocks = (N_NODES + BM - 1) / BM;
        fused_kernel<<<blocks, 256, DSMEM_BYTES>>>(x, b2, out);
    }
    // edge scatter-add
    {
        const long long total = E * 10;
        edge_kernel<<<(int)((total + 255) / 256), 256>>>(erow, ecol, eval, out, E);
    }
    // log_softmax
    {
        const long long threads = (long long)N_NODES * 32;
        logsoftmax_kernel<<<(int)((threads + 255) / 256), 256>>>(out);
    }
}